// round 1
// baseline (speedup 1.0000x reference)
#include <cuda_runtime.h>

#define PRED  96
#define SEQ   512
#define NCH   321
#define NB    64
#define NQ    96          // 48 gathered seasonal rows + 48 trend rows
#define KTOT  608         // 512 + 96
#define NDICT 2000

// ---------------- device scratch (no allocs allowed) ----------------
__device__ float g_Wcs[PRED * SEQ];
__device__ float g_Wct[PRED * SEQ];
__device__ float g_vs[PRED];
__device__ float g_vt[PRED];
__device__ float g_W[PRED * KTOT];    // [A(96x512) | Rall(96x96)]
__device__ float g_bias[PRED];
__device__ float g_G[NB * NQ * NCH];  // gathered dict rows, [b][q][c]

// map q' in [0,48) -> (dict index i, period g, rws inner dim, qq)
__device__ __forceinline__ void qmap(int q, int &i, int &g, int &dim, int &qq) {
    if (q < 24)      { i = 0; g = 4;  dim = 24; qq = q;      }
    else if (q < 36) { i = 1; g = 8;  dim = 12; qq = q - 24; }
    else if (q < 44) { i = 2; g = 12; dim = 8;  qq = q - 36; }
    else             { i = 3; g = 24; dim = 4;  qq = q - 44; }
}

// ---------------- precompute: Wcs = wfs[:, :96] @ wxs ; Wct likewise ----------------
__global__ void k_wc(const float* __restrict__ wxs, const float* __restrict__ wxt,
                     const float* __restrict__ wfs, const float* __restrict__ wft) {
    int id = blockIdx.x * blockDim.x + threadIdx.x;
    if (id >= 2 * PRED * SEQ) return;
    int m = id / (PRED * SEQ);
    int r = id - m * (PRED * SEQ);
    int p = r / SEQ, l = r % SEQ;
    const float* wf = m ? wft : wfs;
    const float* wx = m ? wxt : wxs;
    float s = 0.f;
    #pragma unroll 4
    for (int j = 0; j < PRED; ++j)
        s += wf[p * (2 * PRED) + j] * wx[j * SEQ + l];
    (m ? g_Wct : g_Wcs)[r] = s;
}

// row sums vs[p] = sum_l Wcs[p,l], vt likewise
__global__ void k_v() {
    int id = threadIdx.x;
    if (id >= 2 * PRED) return;
    int m = id / PRED, p = id % PRED;
    const float* W = m ? g_Wct : g_Wcs;
    float s = 0.f;
    for (int l = 0; l < SEQ; ++l) s += W[p * SEQ + l];
    (m ? g_vt : g_vs)[p] = s;
}

// A[p,j] = Wcs[p,j] + ((Wct-Wcs)@M)[p,j] + [j==511](1-vs[p]) + m_last[j]*(vs[p]-vt[p])
__global__ void k_A() {
    int id = blockIdx.x * blockDim.x + threadIdx.x;
    if (id >= PRED * SEQ) return;
    int p = id / SEQ, j = id % SEQ;
    float s = g_Wcs[p * SEQ + j];
    int lo = (j - 12 < 0) ? 0 : j - 12;
    int hi = (j + 12 > SEQ - 1) ? SEQ - 1 : j + 12;
    for (int l = lo; l <= hi; ++l) {
        float cnt = 1.f;
        if (j == 0)       cnt = (float)(13 - l);        // front-clamp multiplicity
        if (j == SEQ - 1) cnt = (float)(l - (SEQ - 14));// back-clamp: l - 498
        s += (g_Wct[p * SEQ + l] - g_Wcs[p * SEQ + l]) * cnt * 0.04f;
    }
    float vs = g_vs[p], vt = g_vt[p];
    float ml = 0.f;
    if (j >= SEQ - 13 && j <= SEQ - 2) ml = 0.04f;      // m_last[499..510] = 1/25
    if (j == SEQ - 1)                  ml = 0.52f;      // m_last[511] = 13/25
    s += ml * (vs - vt);
    if (j == SEQ - 1) s += 1.f - vs;
    g_W[p * KTOT + j] = s;
}

// Rall[p,q] = wf_r @ rw_i  (folded final-layer x ret weights)
__global__ void k_R(const float* __restrict__ wfs, const float* __restrict__ wft,
                    const float* __restrict__ rws0, const float* __restrict__ rws1,
                    const float* __restrict__ rws2, const float* __restrict__ rws3,
                    const float* __restrict__ rwt0, const float* __restrict__ rwt1,
                    const float* __restrict__ rwt2, const float* __restrict__ rwt3) {
    int id = blockIdx.x * blockDim.x + threadIdx.x;
    if (id >= PRED * NQ) return;
    int p = id / NQ, q = id % NQ;
    int side = q / 48, q2 = q % 48;
    int i, g, dim, qq; qmap(q2, i, g, dim, qq);
    const float* wf = side ? wft : wfs;
    const float* rw;
    if (side == 0) rw = (i == 0) ? rws0 : (i == 1) ? rws1 : (i == 2) ? rws2 : rws3;
    else           rw = (i == 0) ? rwt0 : (i == 1) ? rwt1 : (i == 2) ? rwt2 : rwt3;
    float s = 0.f;
    for (int j = 0; j < PRED; ++j)
        s += wf[p * (2 * PRED) + PRED + j] * rw[j * dim + qq];
    g_W[p * KTOT + SEQ + q] = s;
}

// bias[p] = bfs+bft + wf_x@bx + wf_r@(sum rbs) for both rafts
__global__ void k_bias(const float* __restrict__ wfs, const float* __restrict__ wft,
                       const float* __restrict__ bxs, const float* __restrict__ bxt,
                       const float* __restrict__ bfs, const float* __restrict__ bft,
                       const float* __restrict__ rbs0, const float* __restrict__ rbs1,
                       const float* __restrict__ rbs2, const float* __restrict__ rbs3,
                       const float* __restrict__ rbt0, const float* __restrict__ rbt1,
                       const float* __restrict__ rbt2, const float* __restrict__ rbt3) {
    int p = blockIdx.x * blockDim.x + threadIdx.x;
    if (p >= PRED) return;
    float s = bfs[p] + bft[p];
    for (int j = 0; j < PRED; ++j) {
        s += wfs[p * (2 * PRED) + j] * bxs[j] + wft[p * (2 * PRED) + j] * bxt[j];
        s += wfs[p * (2 * PRED) + PRED + j] * (rbs0[j] + rbs1[j] + rbs2[j] + rbs3[j]);
        s += wft[p * (2 * PRED) + PRED + j] * (rbt0[j] + rbt1[j] + rbt2[j] + rbt3[j]);
    }
    g_bias[p] = s;
}

// gather rows q*g of r_dict_{s,t}[i, index[b]] into g_G[b][q][c]
__global__ void k_gather(const float* __restrict__ rds, const float* __restrict__ rdt,
                         const int* __restrict__ index) {
    int id = blockIdx.x * blockDim.x + threadIdx.x;
    if (id >= NB * NQ * NCH) return;
    int c = id % NCH;
    int t = id / NCH;
    int q = t % NQ;
    int b = t / NQ;
    int side = q / 48, q2 = q % 48;
    int i, g, dim, qq; qmap(q2, i, g, dim, qq);
    int row = qq * g;
    const float* d = side ? rdt : rds;
    long src = (((long)i * NDICT + index[b]) * PRED + row) * NCH + c;
    g_G[id] = d[src];
}

// ---------------- main fused GEMM: out = W(96x608) @ X(608 x 20544) + bias ----------------
// grid = 321 blocks x 256 threads; each block: 96p x 64 cols, thread = 6p x 4c.
__global__ __launch_bounds__(256, 3) void k_main(const float* __restrict__ x,
                                                 float* __restrict__ out) {
    __shared__ float xs[32 * 64];      // X chunk [k][c]
    __shared__ float ws[96 * 33];      // W chunk [p][k], padded row 33 (bank-conflict free)
    __shared__ int sxb[64], sgb[64], sob[64];

    int tid = threadIdx.x;
    int j0 = blockIdx.x * 64;
    if (tid < 64) {
        int j = j0 + tid;
        int b = j / NCH, c = j - b * NCH;
        sxb[tid] = b * SEQ * NCH + c;
        sgb[tid] = b * NQ * NCH + c;
        sob[tid] = b * PRED * NCH + c;
    }
    __syncthreads();

    int tp = tid >> 4;     // 0..15  -> p = tp*6 + u
    int tc = tid & 15;     // 0..15  -> c = tc*4 + v

    float acc[6][4];
    #pragma unroll
    for (int u = 0; u < 6; ++u)
        #pragma unroll
        for (int v = 0; v < 4; ++v) acc[u][v] = 0.f;

    float rx[8], rw[12];
    // prefetch chunk 0 (k < 512 -> always x_enc)
    #pragma unroll
    for (int i = 0; i < 12; ++i) {
        int idx = tid + i * 256;
        rw[i] = g_W[(idx >> 5) * KTOT + (idx & 31)];
    }
    #pragma unroll
    for (int i = 0; i < 8; ++i) {
        int idx = tid + i * 256;
        int r = idx >> 6, cc = idx & 63;
        rx[i] = x[sxb[cc] + r * NCH];
    }

    for (int kc = 0; kc < 19; ++kc) {
        __syncthreads();
        #pragma unroll
        for (int i = 0; i < 12; ++i) {
            int idx = tid + i * 256;
            ws[(idx >> 5) * 33 + (idx & 31)] = rw[i];
        }
        #pragma unroll
        for (int i = 0; i < 8; ++i) {
            int idx = tid + i * 256;
            xs[(idx >> 6) * 64 + (idx & 63)] = rx[i];
        }
        __syncthreads();

        if (kc < 18) {                           // prefetch next chunk during compute
            int k0 = (kc + 1) * 32;
            #pragma unroll
            for (int i = 0; i < 12; ++i) {
                int idx = tid + i * 256;
                rw[i] = g_W[(idx >> 5) * KTOT + k0 + (idx & 31)];
            }
            #pragma unroll
            for (int i = 0; i < 8; ++i) {
                int idx = tid + i * 256;
                int r = idx >> 6, cc = idx & 63;
                int k = k0 + r;
                rx[i] = (k < SEQ) ? x[sxb[cc] + k * NCH]
                                  : g_G[sgb[cc] + (k - SEQ) * NCH];
            }
        }

        #pragma unroll
        for (int kl = 0; kl < 32; ++kl) {
            float4 xv = *reinterpret_cast<const float4*>(&xs[kl * 64 + tc * 4]);
            #pragma unroll
            for (int u = 0; u < 6; ++u) {
                float w = ws[(tp * 6 + u) * 33 + kl];
                acc[u][0] += w * xv.x;
                acc[u][1] += w * xv.y;
                acc[u][2] += w * xv.z;
                acc[u][3] += w * xv.w;
            }
        }
    }

    #pragma unroll
    for (int u = 0; u < 6; ++u) {
        int p = tp * 6 + u;
        float bb = g_bias[p];
        #pragma unroll
        for (int v = 0; v < 4; ++v) {
            int cc = tc * 4 + v;
            out[sob[cc] + p * NCH] = acc[u][v] + bb;
        }
    }
}

// ---------------- launch ----------------
extern "C" void kernel_launch(void* const* d_in, const int* in_sizes, int n_in,
                              void* d_out, int out_size) {
    const float* x   = (const float*)d_in[0];
    const int*   idx = (const int*)d_in[1];
    const float* rds = (const float*)d_in[2];
    const float* rdt = (const float*)d_in[3];
    const float* wxs = (const float*)d_in[4];
    const float* bxs = (const float*)d_in[5];
    const float* wxt = (const float*)d_in[6];
    const float* bxt = (const float*)d_in[7];

    const float *wfs, *bfs, *wft, *bft;
    const float *rws[4], *rbs[4], *rwt[4], *rbt[4];

    if (in_sizes[8] == PRED * 2 * PRED) {
        // setup_inputs dict order: wfs,bfs,wft,bft at 8..11 then (rws,rbs,rwt,rbt) x4
        wfs = (const float*)d_in[8];  bfs = (const float*)d_in[9];
        wft = (const float*)d_in[10]; bft = (const float*)d_in[11];
        for (int i = 0; i < 4; ++i) {
            rws[i] = (const float*)d_in[12 + 4 * i];
            rbs[i] = (const float*)d_in[13 + 4 * i];
            rwt[i] = (const float*)d_in[14 + 4 * i];
            rbt[i] = (const float*)d_in[15 + 4 * i];
        }
    } else {
        // reference signature order: rws0..3, rbs0..3, rwt0..3, rbt0..3, wfs,bfs,wft,bft
        for (int i = 0; i < 4; ++i) {
            rws[i] = (const float*)d_in[8 + i];
            rbs[i] = (const float*)d_in[12 + i];
            rwt[i] = (const float*)d_in[16 + i];
            rbt[i] = (const float*)d_in[20 + i];
        }
        wfs = (const float*)d_in[24]; bfs = (const float*)d_in[25];
        wft = (const float*)d_in[26]; bft = (const float*)d_in[27];
    }

    float* out = (float*)d_out;

    k_wc   <<<(2 * PRED * SEQ + 255) / 256, 256>>>(wxs, wxt, wfs, wft);
    k_v    <<<1, 256>>>();
    k_A    <<<(PRED * SEQ + 255) / 256, 256>>>();
    k_R    <<<(PRED * NQ + 255) / 256, 256>>>(wfs, wft,
                rws[0], rws[1], rws[2], rws[3],
                rwt[0], rwt[1], rwt[2], rwt[3]);
    k_bias <<<1, 128>>>(wfs, wft, bxs, bxt, bfs, bft,
                rbs[0], rbs[1], rbs[2], rbs[3],
                rbt[0], rbt[1], rbt[2], rbt[3]);
    k_gather<<<(NB * NQ * NCH + 255) / 256, 256>>>(rds, rdt, idx);
    k_main <<<321, 256>>>(x, out);
}

// round 2
// speedup vs baseline: 1.5001x; 1.5001x over previous
#include <cuda_runtime.h>
#include <cstdint>

#define PRED  96
#define SEQ   512
#define NCH   321
#define NB    64
#define KTOT  608
#define NDICT 2000
#define NTILE 642          // 20544 / 32

// ---------------- device scratch ----------------
__device__ float g_Wt[KTOT * PRED];   // k-major: g_Wt[k*96 + p]
__device__ float g_bias[PRED];

__device__ __forceinline__ void qmap(int q, int &i, int &g, int &dim, int &qq) {
    if (q < 24)      { i = 0; g = 4;  dim = 24; qq = q;      }
    else if (q < 36) { i = 1; g = 8;  dim = 12; qq = q - 24; }
    else if (q < 44) { i = 2; g = 12; dim = 8;  qq = q - 36; }
    else             { i = 3; g = 24; dim = 4;  qq = q - 44; }
}

// ---------------- cp.async helpers ----------------
__device__ __forceinline__ void cpa4(uint32_t d, const void* s) {
    asm volatile("cp.async.ca.shared.global [%0], [%1], 4;" :: "r"(d), "l"(s));
}
__device__ __forceinline__ void cpa16(uint32_t d, const void* s) {
    asm volatile("cp.async.cg.shared.global [%0], [%1], 16;" :: "r"(d), "l"(s));
}
__device__ __forceinline__ void cp_commit() { asm volatile("cp.async.commit_group;"); }
__device__ __forceinline__ void cp_wait1()  { asm volatile("cp.async.wait_group 1;"); }
__device__ __forceinline__ void cp_wait0()  { asm volatile("cp.async.wait_group 0;"); }

// ---------------- fused Wc + rowsum + A : one block per p ----------------
__global__ void k_WA(const float* __restrict__ wxs, const float* __restrict__ wxt,
                     const float* __restrict__ wfs, const float* __restrict__ wft) {
    __shared__ float sfs[96], sft[96];
    __shared__ float scs[512], sct[512];
    __shared__ float r1[16], r2[16];
    __shared__ float svs, svt;
    int p = blockIdx.x, l = threadIdx.x;
    if (l < 96) { sfs[l] = wfs[p * 192 + l]; sft[l] = wft[p * 192 + l]; }
    __syncthreads();
    float cs = 0.f, ct = 0.f;
    #pragma unroll 8
    for (int j = 0; j < 96; ++j) {
        cs += sfs[j] * wxs[j * SEQ + l];
        ct += sft[j] * wxt[j * SEQ + l];
    }
    scs[l] = cs; sct[l] = ct;
    float a = cs, b = ct;
    for (int o = 16; o; o >>= 1) {
        a += __shfl_down_sync(0xffffffffu, a, o);
        b += __shfl_down_sync(0xffffffffu, b, o);
    }
    if ((l & 31) == 0) { r1[l >> 5] = a; r2[l >> 5] = b; }
    __syncthreads();
    if (l == 0) {
        float s1 = 0.f, s2 = 0.f;
        for (int i = 0; i < 16; ++i) { s1 += r1[i]; s2 += r2[i]; }
        svs = s1; svt = s2;
    }
    __syncthreads();
    float vs = svs, vt = svt;
    int lo = (l - 12 < 0) ? 0 : l - 12;
    int hi = (l + 12 > 511) ? 511 : l + 12;
    float s = cs;
    for (int m = lo; m <= hi; ++m) {
        float cnt = 1.f;
        if (l == 0)   cnt = (float)(13 - m);
        if (l == 511) cnt = (float)(m - 498);
        s += (sct[m] - scs[m]) * cnt * 0.04f;
    }
    float ml = 0.f;
    if (l >= 499 && l <= 510) ml = 0.04f;
    if (l == 511)             ml = 0.52f;
    s += ml * (vs - vt);
    if (l == 511) s += 1.f - vs;
    g_Wt[l * 96 + p] = s;
}

// ---------------- fused Rall + bias : blocks 0..95 = R column q, block 96 = bias ----------------
__global__ void k_Rb(const float* __restrict__ wfs, const float* __restrict__ wft,
    const float* __restrict__ rws0, const float* __restrict__ rws1,
    const float* __restrict__ rws2, const float* __restrict__ rws3,
    const float* __restrict__ rwt0, const float* __restrict__ rwt1,
    const float* __restrict__ rwt2, const float* __restrict__ rwt3,
    const float* __restrict__ bxs,  const float* __restrict__ bxt,
    const float* __restrict__ bfs,  const float* __restrict__ bft,
    const float* __restrict__ rbs0, const float* __restrict__ rbs1,
    const float* __restrict__ rbs2, const float* __restrict__ rbs3,
    const float* __restrict__ rbt0, const float* __restrict__ rbt1,
    const float* __restrict__ rbt2, const float* __restrict__ rbt3) {
    int tid = threadIdx.x;
    if (blockIdx.x < 96) {
        __shared__ float srw[96];
        __shared__ float swf[96 * 97];
        int q = blockIdx.x;
        int side = q / 48;
        int i, g, dim, qq; qmap(q % 48, i, g, dim, qq);
        const float* wf = side ? wft : wfs;
        const float* rw;
        if (!side) rw = (i == 0) ? rws0 : (i == 1) ? rws1 : (i == 2) ? rws2 : rws3;
        else       rw = (i == 0) ? rwt0 : (i == 1) ? rwt1 : (i == 2) ? rwt2 : rwt3;
        if (tid < 96) srw[tid] = rw[tid * dim + qq];
        for (int idx = tid; idx < 96 * 96; idx += blockDim.x) {
            int pp = idx / 96, jj = idx - pp * 96;
            swf[pp * 97 + jj] = wf[pp * 192 + 96 + jj];
        }
        __syncthreads();
        if (tid < 96) {
            float s = 0.f;
            #pragma unroll 8
            for (int j = 0; j < 96; ++j) s += swf[tid * 97 + j] * srw[j];
            g_Wt[(512 + q) * 96 + tid] = s;
        }
    } else {
        if (tid < 96) {
            float s = bfs[tid] + bft[tid];
            for (int j = 0; j < 96; ++j) {
                s += wfs[tid * 192 + j] * bxs[j] + wft[tid * 192 + j] * bxt[j];
                s += wfs[tid * 192 + 96 + j] * (rbs0[j] + rbs1[j] + rbs2[j] + rbs3[j]);
                s += wft[tid * 192 + 96 + j] * (rbt0[j] + rbt1[j] + rbt2[j] + rbt3[j]);
            }
            g_bias[tid] = s;
        }
    }
}

// ---------------- main GEMM: out(96 x 20544) = Wt^T @ X + bias ----------------
// 642 blocks x 96 threads; tile 96p x 32c; thread tile 8p x 4c; cp.async double buffer.
__global__ __launch_bounds__(96) void k_main(
    const float* __restrict__ x, const float* __restrict__ rds,
    const float* __restrict__ rdt, const int* __restrict__ index,
    float* __restrict__ out) {
    __shared__ alignas(16) float ws[2][32][100];  // [buf][k][p] padded
    __shared__ alignas(16) float xs[2][32][32];   // [buf][k][c]
    __shared__ int sxb[32], sob[32], sdb[32];
    __shared__ const float* qptr[96];

    int tid = threadIdx.x;
    int j0 = blockIdx.x * 32;
    if (tid < 32) {
        int j = j0 + tid;
        int b = j / NCH, c = j - b * NCH;
        sxb[tid] = b * SEQ * NCH + c;
        sob[tid] = b * PRED * NCH + c;
        sdb[tid] = index[b] * PRED * NCH + c;
    }
    {
        int q = tid;   // blockDim == 96
        int i, g, dim, qq; qmap(q % 48, i, g, dim, qq);
        const float* base = (q < 48) ? rds : rdt;
        qptr[q] = base + i * (NDICT * PRED * NCH) + qq * g * NCH;
    }
    __syncthreads();

    int tp = tid >> 3, tc = tid & 7;
    int ccol = tid & 31;        // fixed column this thread loads
    int kbase = tid >> 5;       // 0..2
    const float* xcol = x + sxb[ccol];
    int doff = sdb[ccol];

    float acc[8][4];
    #pragma unroll
    for (int u = 0; u < 8; ++u)
        #pragma unroll
        for (int v = 0; v < 4; ++v) acc[u][v] = 0.f;

    uint32_t wsb[2] = { (uint32_t)__cvta_generic_to_shared(&ws[0][0][0]),
                        (uint32_t)__cvta_generic_to_shared(&ws[1][0][0]) };
    uint32_t xsb[2] = { (uint32_t)__cvta_generic_to_shared(&xs[0][0][0]),
                        (uint32_t)__cvta_generic_to_shared(&xs[1][0][0]) };

    // ---- load macros ----
    #define LOADW(buf, kc) do {                                             \
        const float* _src = &g_Wt[(kc) * 32 * 96];                          \
        _Pragma("unroll")                                                   \
        for (int i_ = 0; i_ < 8; ++i_) {                                    \
            int idx = tid + i_ * 96;                                        \
            int kk = idx / 24, p4 = idx - kk * 24;                          \
            cpa16(wsb[buf] + (uint32_t)(kk * 100 + p4 * 4) * 4,             \
                  _src + idx * 4);                                          \
        }                                                                   \
    } while (0)

    #define LOADX(buf, kc) do {                                             \
        if ((kc) < 16) {                                                    \
            const float* _s0 = xcol + (kc) * 32 * NCH;                      \
            _Pragma("unroll")                                               \
            for (int i_ = 0; i_ < 11; ++i_) {                               \
                int kk = kbase + i_ * 3;                                    \
                if (kk < 32)                                                \
                    cpa4(xsb[buf] + (uint32_t)(kk * 32 + ccol) * 4,         \
                         _s0 + kk * NCH);                                   \
            }                                                               \
        } else {                                                            \
            int q0 = ((kc) - 16) * 32;                                      \
            _Pragma("unroll")                                               \
            for (int i_ = 0; i_ < 11; ++i_) {                               \
                int kk = kbase + i_ * 3;                                    \
                if (kk < 32)                                                \
                    cpa4(xsb[buf] + (uint32_t)(kk * 32 + ccol) * 4,         \
                         qptr[q0 + kk] + doff);                             \
            }                                                               \
        }                                                                   \
    } while (0)

    LOADW(0, 0); LOADX(0, 0); cp_commit();

    #pragma unroll 1
    for (int kc = 0; kc < 19; ++kc) {
        int cur = kc & 1;
        if (kc < 18) {
            int nxt = cur ^ 1;
            LOADW(nxt, kc + 1); LOADX(nxt, kc + 1); cp_commit();
            cp_wait1();
        } else {
            cp_wait0();
        }
        __syncthreads();
        #pragma unroll
        for (int kl = 0; kl < 32; ++kl) {
            float4 xv = *reinterpret_cast<const float4*>(&xs[cur][kl][tc * 4]);
            float4 wa = *reinterpret_cast<const float4*>(&ws[cur][kl][tp * 8]);
            float4 wb = *reinterpret_cast<const float4*>(&ws[cur][kl][tp * 8 + 4]);
            float wv[8] = { wa.x, wa.y, wa.z, wa.w, wb.x, wb.y, wb.z, wb.w };
            #pragma unroll
            for (int u = 0; u < 8; ++u) {
                acc[u][0] += wv[u] * xv.x;
                acc[u][1] += wv[u] * xv.y;
                acc[u][2] += wv[u] * xv.z;
                acc[u][3] += wv[u] * xv.w;
            }
        }
        __syncthreads();
    }
    #undef LOADW
    #undef LOADX

    #pragma unroll
    for (int u = 0; u < 8; ++u) {
        int p = tp * 8 + u;
        float bb = g_bias[p];
        int rowoff = p * NCH;
        #pragma unroll
        for (int v = 0; v < 4; ++v)
            out[sob[tc * 4 + v] + rowoff] = acc[u][v] + bb;
    }
}

// ---------------- launch ----------------
extern "C" void kernel_launch(void* const* d_in, const int* in_sizes, int n_in,
                              void* d_out, int out_size) {
    const float* x   = (const float*)d_in[0];
    const int*   idx = (const int*)d_in[1];
    const float* rds = (const float*)d_in[2];
    const float* rdt = (const float*)d_in[3];
    const float* wxs = (const float*)d_in[4];
    const float* bxs = (const float*)d_in[5];
    const float* wxt = (const float*)d_in[6];
    const float* bxt = (const float*)d_in[7];

    const float *wfs, *bfs, *wft, *bft;
    const float *rws[4], *rbs[4], *rwt[4], *rbt[4];

    if (in_sizes[8] == PRED * 2 * PRED) {
        wfs = (const float*)d_in[8];  bfs = (const float*)d_in[9];
        wft = (const float*)d_in[10]; bft = (const float*)d_in[11];
        for (int i = 0; i < 4; ++i) {
            rws[i] = (const float*)d_in[12 + 4 * i];
            rbs[i] = (const float*)d_in[13 + 4 * i];
            rwt[i] = (const float*)d_in[14 + 4 * i];
            rbt[i] = (const float*)d_in[15 + 4 * i];
        }
    } else {
        for (int i = 0; i < 4; ++i) {
            rws[i] = (const float*)d_in[8 + i];
            rbs[i] = (const float*)d_in[12 + i];
            rwt[i] = (const float*)d_in[16 + i];
            rbt[i] = (const float*)d_in[20 + i];
        }
        wfs = (const float*)d_in[24]; bfs = (const float*)d_in[25];
        wft = (const float*)d_in[26]; bft = (const float*)d_in[27];
    }

    float* out = (float*)d_out;

    k_WA<<<96, 512>>>(wxs, wxt, wfs, wft);
    k_Rb<<<97, 128>>>(wfs, wft,
                      rws[0], rws[1], rws[2], rws[3],
                      rwt[0], rwt[1], rwt[2], rwt[3],
                      bxs, bxt, bfs, bft,
                      rbs[0], rbs[1], rbs[2], rbs[3],
                      rbt[0], rbt[1], rbt[2], rbt[3]);
    k_main<<<NTILE, 96>>>(x, rds, rdt, idx, out);
}

// round 3
// speedup vs baseline: 2.0531x; 1.3686x over previous
#include <cuda_runtime.h>
#include <cstdint>

#define PRED  96
#define SEQ   512
#define NCH   321
#define NB    64
#define KTOT  608
#define NDICT 2000

// ---------------- device scratch ----------------
__device__ float g_Wt[KTOT * PRED];     // k-major: g_Wt[col*96 + p]
__device__ float g_bias[PRED];
__device__ float g_B[192 * KTOT];       // B operand for precompute GEMM, [j][col]
__device__ float g_Ax[192 * PRED];      // [j][p] = x-half of wf (s rows 0..95, t rows 96..191)
__device__ float g_Ar[192 * PRED];      // [j][p] = r-half of wf

__device__ __forceinline__ void qmap(int q, int &i, int &g, int &dim, int &qq) {
    if (q < 24)      { i = 0; g = 4;  dim = 24; qq = q;      }
    else if (q < 36) { i = 1; g = 8;  dim = 12; qq = q - 24; }
    else if (q < 44) { i = 2; g = 12; dim = 8;  qq = q - 36; }
    else             { i = 3; g = 24; dim = 4;  qq = q - 44; }
}

// ---------------- f32x2 helpers ----------------
__device__ __forceinline__ unsigned long long bcast2(float w) {
    unsigned long long r;
    asm("mov.b64 %0, {%1, %1};" : "=l"(r) : "f"(w));
    return r;
}
__device__ __forceinline__ void fma2(unsigned long long &d, unsigned long long a,
                                     unsigned long long b) {
    asm("fma.rn.f32x2 %0, %1, %2, %0;" : "+l"(d) : "l"(a), "l"(b));
}
__device__ __forceinline__ void unpack2(unsigned long long v, float &lo, float &hi) {
    asm("mov.b64 {%0, %1}, %2;" : "=f"(lo), "=f"(hi) : "l"(v));
}

// ---------------- cp.async helpers ----------------
__device__ __forceinline__ void cpa4(uint32_t d, const void* s) {
    asm volatile("cp.async.ca.shared.global [%0], [%1], 4;" :: "r"(d), "l"(s));
}
__device__ __forceinline__ void cpa16(uint32_t d, const void* s) {
    asm volatile("cp.async.cg.shared.global [%0], [%1], 16;" :: "r"(d), "l"(s));
}
__device__ __forceinline__ void cp_commit() { asm volatile("cp.async.commit_group;"); }
__device__ __forceinline__ void cp_wait1()  { asm volatile("cp.async.wait_group 1;"); }
__device__ __forceinline__ void cp_wait0()  { asm volatile("cp.async.wait_group 0;"); }

// ================= k_prep =================
// blocks 0..191: build g_B row j (banded op on wx row + rank-1 fold + R columns)
//                and transpose wf into g_Ax / g_Ar.
// block 192: bias.
__global__ void k_prep(const float* __restrict__ wxs, const float* __restrict__ wxt,
    const float* __restrict__ wfs, const float* __restrict__ wft,
    const float* __restrict__ rws0, const float* __restrict__ rws1,
    const float* __restrict__ rws2, const float* __restrict__ rws3,
    const float* __restrict__ rwt0, const float* __restrict__ rwt1,
    const float* __restrict__ rwt2, const float* __restrict__ rwt3,
    const float* __restrict__ bxs,  const float* __restrict__ bxt,
    const float* __restrict__ bfs,  const float* __restrict__ bft,
    const float* __restrict__ rbs0, const float* __restrict__ rbs1,
    const float* __restrict__ rbs2, const float* __restrict__ rbs3,
    const float* __restrict__ rbt0, const float* __restrict__ rbt1,
    const float* __restrict__ rbt2, const float* __restrict__ rbt3) {
    int tid = threadIdx.x;
    if (blockIdx.x == 192) {
        if (tid < 96) {
            float s = bfs[tid] + bft[tid];
            for (int j = 0; j < 96; ++j) {
                s += wfs[tid * 192 + j] * bxs[j] + wft[tid * 192 + j] * bxt[j];
                s += wfs[tid * 192 + 96 + j] * (rbs0[j] + rbs1[j] + rbs2[j] + rbs3[j]);
                s += wft[tid * 192 + 96 + j] * (rbt0[j] + rbt1[j] + rbt2[j] + rbt3[j]);
            }
            g_bias[tid] = s;
        }
        return;
    }
    __shared__ float r[512];
    __shared__ float red[8];
    __shared__ float s_su;
    int j = blockIdx.x;
    int side = j / 96, row = j % 96;
    const float* wx = side ? wxt : wxs;
    r[tid]       = wx[row * SEQ + tid];
    r[tid + 256] = wx[row * SEQ + tid + 256];
    __syncthreads();
    // row sum
    {
        float a = r[tid] + r[tid + 256];
        for (int o = 16; o; o >>= 1) a += __shfl_down_sync(0xffffffffu, a, o);
        if ((tid & 31) == 0) red[tid >> 5] = a;
        __syncthreads();
        if (tid == 0) {
            float s = 0.f;
            #pragma unroll
            for (int i = 0; i < 8; ++i) s += red[i];
            s_su = s;
        }
        __syncthreads();
    }
    float su = s_su;
    // banded moving-average operator column + rank-1 fold
    #pragma unroll
    for (int t = 0; t < 2; ++t) {
        int l = tid + t * 256;
        int lo = (l - 12 < 0) ? 0 : l - 12;
        int hi = (l + 12 > 511) ? 511 : l + 12;
        float band = 0.f;
        for (int m = lo; m <= hi; ++m) {
            float cnt = 1.f;
            if (l == 0)   cnt = (float)(13 - m);
            if (l == 511) cnt = (float)(m - 498);
            band += cnt * r[m];
        }
        band *= 0.04f;
        float v = side ? band : (r[l] - band);
        float ml = 0.f;
        if (l >= 499 && l <= 510) ml = 0.04f;
        if (l == 511)             ml = 0.52f;
        float coef = side ? (-ml) : (ml - (l == 511 ? 1.f : 0.f));
        v += su * coef;
        g_B[j * KTOT + l] = v;
    }
    // R columns of B
    if (tid < 96) {
        int q = tid;
        int i, g, dim, qq; qmap(q % 48, i, g, dim, qq);
        float rv = 0.f;
        if ((q / 48) == side) {
            const float* rw;
            if (!side) rw = (i == 0) ? rws0 : (i == 1) ? rws1 : (i == 2) ? rws2 : rws3;
            else       rw = (i == 0) ? rwt0 : (i == 1) ? rwt1 : (i == 2) ? rwt2 : rwt3;
            rv = rw[row * dim + qq];
        }
        g_B[j * KTOT + 512 + q] = rv;
    }
    // transpose wf halves: g_Ax[j][p], g_Ar[j][p]
    if (tid < 96) {
        const float* wf = side ? wft : wfs;
        g_Ax[j * 96 + tid] = wf[tid * 192 + row];
        g_Ar[j * 96 + tid] = wf[tid * 192 + 96 + row];
    }
}

// ================= k_pgemm =================
// g_Wt[col][p] = sum_j A[j][p] * g_B[j][col];  A = g_Ax for col<512, g_Ar for col>=512.
// 76 blocks x 128 threads; tile 96p x 8col; thread 3p x 2col; K=192 in 6 chunks of 32.
__global__ __launch_bounds__(128) void k_pgemm() {
    __shared__ float sA[32 * 96];
    __shared__ float sB[32][8];
    int tid = threadIdx.x;
    int col0 = blockIdx.x * 8;
    const float* A = (col0 >= 512) ? g_Ar : g_Ax;
    int tp = tid >> 2;        // 0..31 -> p = tp*3
    int tc = tid & 3;         // 0..3  -> c = tc*2
    float acc[3][2] = {};
    for (int jc = 0; jc < 6; ++jc) {
        __syncthreads();
        const float4* srcA = reinterpret_cast<const float4*>(A + jc * 32 * 96);
        #pragma unroll
        for (int i = 0; i < 6; ++i)
            reinterpret_cast<float4*>(sA)[tid + i * 128] = srcA[tid + i * 128];
        #pragma unroll
        for (int i = 0; i < 2; ++i) {
            int idx = tid + i * 128;
            int jj = idx >> 3, cc = idx & 7;
            sB[jj][cc] = g_B[(jc * 32 + jj) * KTOT + col0 + cc];
        }
        __syncthreads();
        #pragma unroll 8
        for (int jj = 0; jj < 32; ++jj) {
            float b0 = sB[jj][tc * 2], b1 = sB[jj][tc * 2 + 1];
            #pragma unroll
            for (int u = 0; u < 3; ++u) {
                float a = sA[jj * 96 + tp * 3 + u];
                acc[u][0] += a * b0;
                acc[u][1] += a * b1;
            }
        }
    }
    #pragma unroll
    for (int v = 0; v < 2; ++v) {
        int col = col0 + tc * 2 + v;
        float add = (col == 511) ? 1.f : 0.f;
        #pragma unroll
        for (int u = 0; u < 3; ++u)
            g_Wt[col * 96 + tp * 3 + u] = acc[u][v] + add;
    }
}

// ================= k_main =================
// out(96 x 20544) = Wt^T @ X + bias.
// 428 blocks x 128 threads (4 warps); tile 96p x 48c; thread 6p x 6c; f32x2 FMA.
__global__ __launch_bounds__(128) void k_main(
    const float* __restrict__ x, const float* __restrict__ rds,
    const float* __restrict__ rdt, const int* __restrict__ index,
    float* __restrict__ out) {
    __shared__ alignas(16) float ws[2][32][96];   // [buf][k][p]
    __shared__ alignas(16) float xs[2][32][48];   // [buf][k][c]
    __shared__ int sxb[48], sob[48], sdb[48];
    __shared__ const float* qptr[96];

    int tid = threadIdx.x;
    int j0 = blockIdx.x * 48;
    if (tid < 48) {
        int j = j0 + tid;
        int b = j / NCH, c = j - b * NCH;
        sxb[tid] = b * SEQ * NCH + c;
        sob[tid] = b * PRED * NCH + c;
        sdb[tid] = index[b] * PRED * NCH + c;
    }
    if (tid < 96) {
        int q = tid;
        int i, g, dim, qq; qmap(q % 48, i, g, dim, qq);
        const float* base = (q < 48) ? rds : rdt;
        qptr[q] = base + (size_t)i * (NDICT * PRED * NCH) + (size_t)qq * g * NCH;
    }
    __syncthreads();

    int tp = tid >> 3;   // 0..15 -> p = tp*6
    int tc = tid & 7;    // 0..7  -> c = tc*6

    unsigned long long acc[6][3];
    #pragma unroll
    for (int u = 0; u < 6; ++u)
        #pragma unroll
        for (int v = 0; v < 3; ++v) acc[u][v] = 0ull;

    uint32_t wsb[2] = { (uint32_t)__cvta_generic_to_shared(&ws[0][0][0]),
                        (uint32_t)__cvta_generic_to_shared(&ws[1][0][0]) };
    uint32_t xsb[2] = { (uint32_t)__cvta_generic_to_shared(&xs[0][0][0]),
                        (uint32_t)__cvta_generic_to_shared(&xs[1][0][0]) };

    #define LOADW(buf, kc) do {                                             \
        const float* _src = &g_Wt[(kc) * 32 * 96];                          \
        _Pragma("unroll")                                                   \
        for (int i_ = 0; i_ < 6; ++i_) {                                    \
            int idx = tid + i_ * 128;                                       \
            cpa16(wsb[buf] + (uint32_t)idx * 16, _src + idx * 4);           \
        }                                                                   \
    } while (0)

    #define LOADX(buf, kc) do {                                             \
        if ((kc) < 16) {                                                    \
            _Pragma("unroll")                                               \
            for (int i_ = 0; i_ < 12; ++i_) {                               \
                int idx = tid + i_ * 128;                                   \
                int kk = idx / 48, cc = idx - kk * 48;                      \
                cpa4(xsb[buf] + (uint32_t)idx * 4,                          \
                     x + sxb[cc] + ((kc) * 32 + kk) * NCH);                 \
            }                                                               \
        } else {                                                            \
            _Pragma("unroll")                                               \
            for (int i_ = 0; i_ < 12; ++i_) {                               \
                int idx = tid + i_ * 128;                                   \
                int kk = idx / 48, cc = idx - kk * 48;                      \
                cpa4(xsb[buf] + (uint32_t)idx * 4,                          \
                     qptr[((kc) - 16) * 32 + kk] + sdb[cc]);                \
            }                                                               \
        }                                                                   \
    } while (0)

    LOADW(0, 0); LOADX(0, 0); cp_commit();

    #pragma unroll 1
    for (int kc = 0; kc < 19; ++kc) {
        int cur = kc & 1;
        if (kc < 18) {
            int nxt = cur ^ 1;
            LOADW(nxt, kc + 1); LOADX(nxt, kc + 1); cp_commit();
            cp_wait1();
        } else {
            cp_wait0();
        }
        __syncthreads();
        #pragma unroll
        for (int kl = 0; kl < 32; ++kl) {
            // x pairs: 3 x 8-byte smem loads (c packed naturally)
            const float* xrow = &xs[cur][kl][tc * 6];
            unsigned long long xp0 = *reinterpret_cast<const unsigned long long*>(xrow);
            unsigned long long xp1 = *reinterpret_cast<const unsigned long long*>(xrow + 2);
            unsigned long long xp2 = *reinterpret_cast<const unsigned long long*>(xrow + 4);
            const float* wrow = &ws[cur][kl][tp * 6];
            float2 w01 = *reinterpret_cast<const float2*>(wrow);
            float2 w23 = *reinterpret_cast<const float2*>(wrow + 2);
            float2 w45 = *reinterpret_cast<const float2*>(wrow + 4);
            unsigned long long wp[6];
            wp[0] = bcast2(w01.x); wp[1] = bcast2(w01.y);
            wp[2] = bcast2(w23.x); wp[3] = bcast2(w23.y);
            wp[4] = bcast2(w45.x); wp[5] = bcast2(w45.y);
            #pragma unroll
            for (int u = 0; u < 6; ++u) {
                fma2(acc[u][0], wp[u], xp0);
                fma2(acc[u][1], wp[u], xp1);
                fma2(acc[u][2], wp[u], xp2);
            }
        }
        __syncthreads();
    }
    #undef LOADW
    #undef LOADX

    #pragma unroll
    for (int u = 0; u < 6; ++u) {
        int p = tp * 6 + u;
        float bb = g_bias[p];
        int rowoff = p * NCH;
        #pragma unroll
        for (int v = 0; v < 3; ++v) {
            float lo, hi;
            unpack2(acc[u][v], lo, hi);
            out[sob[tc * 6 + v * 2]     + rowoff] = lo + bb;
            out[sob[tc * 6 + v * 2 + 1] + rowoff] = hi + bb;
        }
    }
}

// ---------------- launch ----------------
extern "C" void kernel_launch(void* const* d_in, const int* in_sizes, int n_in,
                              void* d_out, int out_size) {
    const float* x   = (const float*)d_in[0];
    const int*   idx = (const int*)d_in[1];
    const float* rds = (const float*)d_in[2];
    const float* rdt = (const float*)d_in[3];
    const float* wxs = (const float*)d_in[4];
    const float* bxs = (const float*)d_in[5];
    const float* wxt = (const float*)d_in[6];
    const float* bxt = (const float*)d_in[7];

    const float *wfs, *bfs, *wft, *bft;
    const float *rws[4], *rbs[4], *rwt[4], *rbt[4];

    if (in_sizes[8] == PRED * 2 * PRED) {
        wfs = (const float*)d_in[8];  bfs = (const float*)d_in[9];
        wft = (const float*)d_in[10]; bft = (const float*)d_in[11];
        for (int i = 0; i < 4; ++i) {
            rws[i] = (const float*)d_in[12 + 4 * i];
            rbs[i] = (const float*)d_in[13 + 4 * i];
            rwt[i] = (const float*)d_in[14 + 4 * i];
            rbt[i] = (const float*)d_in[15 + 4 * i];
        }
    } else {
        for (int i = 0; i < 4; ++i) {
            rws[i] = (const float*)d_in[8 + i];
            rbs[i] = (const float*)d_in[12 + i];
            rwt[i] = (const float*)d_in[16 + i];
            rbt[i] = (const float*)d_in[20 + i];
        }
        wfs = (const float*)d_in[24]; bfs = (const float*)d_in[25];
        wft = (const float*)d_in[26]; bft = (const float*)d_in[27];
    }

    float* out = (float*)d_out;

    k_prep<<<193, 256>>>(wxs, wxt, wfs, wft,
                         rws[0], rws[1], rws[2], rws[3],
                         rwt[0], rwt[1], rwt[2], rwt[3],
                         bxs, bxt, bfs, bft,
                         rbs[0], rbs[1], rbs[2], rbs[3],
                         rbt[0], rbt[1], rbt[2], rbt[3]);
    k_pgemm<<<76, 128>>>();
    k_main<<<428, 128>>>(x, rds, rdt, idx, out);
}

// round 4
// speedup vs baseline: 2.4528x; 1.1947x over previous
#include <cuda_runtime.h>
#include <cstdint>

#define PRED  96
#define SEQ   512
#define NCH   321
#define NB    64
#define KTOT  608
#define NDICT 2000

// ---------------- device scratch ----------------
__device__ float g_Wd[KTOT * 192];      // duplicated k-major: g_Wd[col*192 + 2p+{0,1}]
__device__ float g_bias[PRED];
__device__ float g_B[192 * KTOT];       // [j][col]
__device__ float g_Ax[192 * PRED];      // [j][p]
__device__ float g_Ar[192 * PRED];      // [j][p]

__device__ __forceinline__ void qmap(int q, int &i, int &g, int &dim, int &qq) {
    if (q < 24)      { i = 0; g = 4;  dim = 24; qq = q;      }
    else if (q < 36) { i = 1; g = 8;  dim = 12; qq = q - 24; }
    else if (q < 44) { i = 2; g = 12; dim = 8;  qq = q - 36; }
    else             { i = 3; g = 24; dim = 4;  qq = q - 44; }
}

// ---------------- f32x2 helpers ----------------
__device__ __forceinline__ void fma2(unsigned long long &d, unsigned long long a,
                                     unsigned long long b) {
    asm("fma.rn.f32x2 %0, %1, %2, %0;" : "+l"(d) : "l"(a), "l"(b));
}
__device__ __forceinline__ void unpack2(unsigned long long v, float &lo, float &hi) {
    asm("mov.b64 {%0, %1}, %2;" : "=f"(lo), "=f"(hi) : "l"(v));
}

// ---------------- cp.async helpers ----------------
__device__ __forceinline__ void cpa4(uint32_t d, const void* s) {
    asm volatile("cp.async.ca.shared.global [%0], [%1], 4;" :: "r"(d), "l"(s));
}
__device__ __forceinline__ void cpa16(uint32_t d, const void* s) {
    asm volatile("cp.async.cg.shared.global [%0], [%1], 16;" :: "r"(d), "l"(s));
}
__device__ __forceinline__ void cp_commit() { asm volatile("cp.async.commit_group;"); }
__device__ __forceinline__ void cp_wait1()  { asm volatile("cp.async.wait_group 1;"); }
__device__ __forceinline__ void cp_wait0()  { asm volatile("cp.async.wait_group 0;"); }

// ================= k_prep =================
// blocks 0..191: build g_B row j + transpose wf into g_Ax/g_Ar.
// blocks 192..287: bias[p], p = blockIdx-192, parallel-reduced over j.
__global__ void k_prep(const float* __restrict__ wxs, const float* __restrict__ wxt,
    const float* __restrict__ wfs, const float* __restrict__ wft,
    const float* __restrict__ rws0, const float* __restrict__ rws1,
    const float* __restrict__ rws2, const float* __restrict__ rws3,
    const float* __restrict__ rwt0, const float* __restrict__ rwt1,
    const float* __restrict__ rwt2, const float* __restrict__ rwt3,
    const float* __restrict__ bxs,  const float* __restrict__ bxt,
    const float* __restrict__ bfs,  const float* __restrict__ bft,
    const float* __restrict__ rbs0, const float* __restrict__ rbs1,
    const float* __restrict__ rbs2, const float* __restrict__ rbs3,
    const float* __restrict__ rbt0, const float* __restrict__ rbt1,
    const float* __restrict__ rbt2, const float* __restrict__ rbt3) {
    int tid = threadIdx.x;
    if (blockIdx.x >= 192) {
        // ---- parallel bias ----
        __shared__ float red[8];
        int p = blockIdx.x - 192;
        float c = 0.f;
        if (tid < 96) {
            int j = tid;
            c = wfs[p * 192 + j] * bxs[j] + wft[p * 192 + j] * bxt[j]
              + wfs[p * 192 + 96 + j] * (rbs0[j] + rbs1[j] + rbs2[j] + rbs3[j])
              + wft[p * 192 + 96 + j] * (rbt0[j] + rbt1[j] + rbt2[j] + rbt3[j]);
        }
        for (int o = 16; o; o >>= 1) c += __shfl_down_sync(0xffffffffu, c, o);
        if ((tid & 31) == 0) red[tid >> 5] = c;
        __syncthreads();
        if (tid == 0) {
            float s = bfs[p] + bft[p];
            #pragma unroll
            for (int i = 0; i < 4; ++i) s += red[i];
            g_bias[p] = s;
        }
        return;
    }
    __shared__ float r[512];
    __shared__ float red[8];
    __shared__ float s_su;
    int j = blockIdx.x;
    int side = j / 96, row = j % 96;
    const float* wx = side ? wxt : wxs;
    r[tid]       = wx[row * SEQ + tid];
    r[tid + 256] = wx[row * SEQ + tid + 256];
    __syncthreads();
    {
        float a = r[tid] + r[tid + 256];
        for (int o = 16; o; o >>= 1) a += __shfl_down_sync(0xffffffffu, a, o);
        if ((tid & 31) == 0) red[tid >> 5] = a;
        __syncthreads();
        if (tid == 0) {
            float s = 0.f;
            #pragma unroll
            for (int i = 0; i < 8; ++i) s += red[i];
            s_su = s;
        }
        __syncthreads();
    }
    float su = s_su;
    #pragma unroll
    for (int t = 0; t < 2; ++t) {
        int l = tid + t * 256;
        int lo = (l - 12 < 0) ? 0 : l - 12;
        int hi = (l + 12 > 511) ? 511 : l + 12;
        float band = 0.f;
        for (int m = lo; m <= hi; ++m) {
            float cnt = 1.f;
            if (l == 0)   cnt = (float)(13 - m);
            if (l == 511) cnt = (float)(m - 498);
            band += cnt * r[m];
        }
        band *= 0.04f;
        float v = side ? band : (r[l] - band);
        float ml = 0.f;
        if (l >= 499 && l <= 510) ml = 0.04f;
        if (l == 511)             ml = 0.52f;
        float coef = side ? (-ml) : (ml - (l == 511 ? 1.f : 0.f));
        v += su * coef;
        g_B[j * KTOT + l] = v;
    }
    if (tid < 96) {
        int q = tid;
        int i, g, dim, qq; qmap(q % 48, i, g, dim, qq);
        float rv = 0.f;
        if ((q / 48) == side) {
            const float* rw;
            if (!side) rw = (i == 0) ? rws0 : (i == 1) ? rws1 : (i == 2) ? rws2 : rws3;
            else       rw = (i == 0) ? rwt0 : (i == 1) ? rwt1 : (i == 2) ? rwt2 : rwt3;
            rv = rw[row * dim + qq];
        }
        g_B[j * KTOT + 512 + q] = rv;
    }
    if (tid < 96) {
        const float* wf = side ? wft : wfs;
        g_Ax[j * 96 + tid] = wf[tid * 192 + row];
        g_Ar[j * 96 + tid] = wf[tid * 192 + 96 + row];
    }
}

// ================= k_pgemm =================
// g_Wd[col][2p,2p+1] = sum_j A[j][p]*g_B[j][col] (+1 at col 511), duplicated store.
__global__ __launch_bounds__(128) void k_pgemm() {
    __shared__ float sA[32 * 96];
    __shared__ float sB[32][8];
    int tid = threadIdx.x;
    int col0 = blockIdx.x * 8;
    const float* A = (col0 >= 512) ? g_Ar : g_Ax;
    int tp = tid >> 2;
    int tc = tid & 3;
    float acc[3][2] = {};
    for (int jc = 0; jc < 6; ++jc) {
        __syncthreads();
        const float4* srcA = reinterpret_cast<const float4*>(A + jc * 32 * 96);
        #pragma unroll
        for (int i = 0; i < 6; ++i)
            reinterpret_cast<float4*>(sA)[tid + i * 128] = srcA[tid + i * 128];
        #pragma unroll
        for (int i = 0; i < 2; ++i) {
            int idx = tid + i * 128;
            int jj = idx >> 3, cc = idx & 7;
            sB[jj][cc] = g_B[(jc * 32 + jj) * KTOT + col0 + cc];
        }
        __syncthreads();
        #pragma unroll 8
        for (int jj = 0; jj < 32; ++jj) {
            float b0 = sB[jj][tc * 2], b1 = sB[jj][tc * 2 + 1];
            #pragma unroll
            for (int u = 0; u < 3; ++u) {
                float a = sA[jj * 96 + tp * 3 + u];
                acc[u][0] += a * b0;
                acc[u][1] += a * b1;
            }
        }
    }
    #pragma unroll
    for (int v = 0; v < 2; ++v) {
        int col = col0 + tc * 2 + v;
        float add = (col == 511) ? 1.f : 0.f;
        #pragma unroll
        for (int u = 0; u < 3; ++u) {
            float val = acc[u][v] + add;
            int p = tp * 3 + u;
            g_Wd[col * 192 + 2 * p]     = val;
            g_Wd[col * 192 + 2 * p + 1] = val;
        }
    }
}

// ================= k_main =================
// out(96 x 20544) = W^T @ X + bias. 428 blocks x 128 threads; tile 96p x 48c;
// thread 6p x 6c; W pre-duplicated -> pure LDS.128/LDS.64 + FFMA2 inner loop.
__global__ __launch_bounds__(128) void k_main(
    const float* __restrict__ x, const float* __restrict__ rds,
    const float* __restrict__ rdt, const int* __restrict__ index,
    float* __restrict__ out) {
    __shared__ alignas(16) float ws[2][32][192];  // duplicated [buf][k][2p]
    __shared__ alignas(16) float xs[2][32][48];
    __shared__ int sxb[48], sob[48], sdb[48];
    __shared__ const float* qptr[96];

    int tid = threadIdx.x;
    int j0 = blockIdx.x * 48;
    if (tid < 48) {
        int j = j0 + tid;
        int b = j / NCH, c = j - b * NCH;
        sxb[tid] = b * SEQ * NCH + c;
        sob[tid] = b * PRED * NCH + c;
        sdb[tid] = index[b] * PRED * NCH + c;
    }
    if (tid < 96) {
        int q = tid;
        int i, g, dim, qq; qmap(q % 48, i, g, dim, qq);
        const float* base = (q < 48) ? rds : rdt;
        qptr[q] = base + (size_t)i * (NDICT * PRED * NCH) + (size_t)qq * g * NCH;
    }
    __syncthreads();

    int tp = tid >> 3;   // 0..15 -> p = tp*6
    int tc = tid & 7;    // 0..7  -> c = tc*6

    unsigned long long acc[6][3];
    #pragma unroll
    for (int u = 0; u < 6; ++u)
        #pragma unroll
        for (int v = 0; v < 3; ++v) acc[u][v] = 0ull;

    uint32_t wsb[2] = { (uint32_t)__cvta_generic_to_shared(&ws[0][0][0]),
                        (uint32_t)__cvta_generic_to_shared(&ws[1][0][0]) };
    uint32_t xsb[2] = { (uint32_t)__cvta_generic_to_shared(&xs[0][0][0]),
                        (uint32_t)__cvta_generic_to_shared(&xs[1][0][0]) };

    #define LOADW(buf, kc) do {                                             \
        const float* _src = &g_Wd[(kc) * 32 * 192];                         \
        _Pragma("unroll")                                                   \
        for (int i_ = 0; i_ < 12; ++i_) {                                   \
            int idx = tid + i_ * 128;                                       \
            cpa16(wsb[buf] + (uint32_t)idx * 16, _src + idx * 4);           \
        }                                                                   \
    } while (0)

    #define LOADX(buf, kc) do {                                             \
        if ((kc) < 16) {                                                    \
            _Pragma("unroll")                                               \
            for (int i_ = 0; i_ < 12; ++i_) {                               \
                int idx = tid + i_ * 128;                                   \
                int kk = idx / 48, cc = idx - kk * 48;                      \
                cpa4(xsb[buf] + (uint32_t)idx * 4,                          \
                     x + sxb[cc] + ((kc) * 32 + kk) * NCH);                 \
            }                                                               \
        } else {                                                            \
            _Pragma("unroll")                                               \
            for (int i_ = 0; i_ < 12; ++i_) {                               \
                int idx = tid + i_ * 128;                                   \
                int kk = idx / 48, cc = idx - kk * 48;                      \
                cpa4(xsb[buf] + (uint32_t)idx * 4,                          \
                     qptr[((kc) - 16) * 32 + kk] + sdb[cc]);                \
            }                                                               \
        }                                                                   \
    } while (0)

    LOADW(0, 0); LOADX(0, 0); cp_commit();

    #pragma unroll 1
    for (int kc = 0; kc < 19; ++kc) {
        int cur = kc & 1;
        if (kc < 18) {
            int nxt = cur ^ 1;
            LOADW(nxt, kc + 1); LOADX(nxt, kc + 1); cp_commit();
            cp_wait1();
        } else {
            cp_wait0();
        }
        __syncthreads();
        #pragma unroll
        for (int kl = 0; kl < 32; ++kl) {
            const unsigned long long* xr =
                reinterpret_cast<const unsigned long long*>(&xs[cur][kl][tc * 6]);
            unsigned long long xp0 = xr[0], xp1 = xr[1], xp2 = xr[2];
            const ulonglong2* wr =
                reinterpret_cast<const ulonglong2*>(&ws[cur][kl][tp * 12]);
            ulonglong2 wq0 = wr[0], wq1 = wr[1], wq2 = wr[2];
            unsigned long long wp[6] = { wq0.x, wq0.y, wq1.x, wq1.y, wq2.x, wq2.y };
            #pragma unroll
            for (int u = 0; u < 6; ++u) {
                fma2(acc[u][0], wp[u], xp0);
                fma2(acc[u][1], wp[u], xp1);
                fma2(acc[u][2], wp[u], xp2);
            }
        }
        __syncthreads();
    }
    #undef LOADW
    #undef LOADX

    #pragma unroll
    for (int u = 0; u < 6; ++u) {
        int p = tp * 6 + u;
        float bb = g_bias[p];
        int rowoff = p * NCH;
        #pragma unroll
        for (int v = 0; v < 3; ++v) {
            float lo, hi;
            unpack2(acc[u][v], lo, hi);
            out[sob[tc * 6 + v * 2]     + rowoff] = lo + bb;
            out[sob[tc * 6 + v * 2 + 1] + rowoff] = hi + bb;
        }
    }
}

// ---------------- launch ----------------
extern "C" void kernel_launch(void* const* d_in, const int* in_sizes, int n_in,
                              void* d_out, int out_size) {
    const float* x   = (const float*)d_in[0];
    const int*   idx = (const int*)d_in[1];
    const float* rds = (const float*)d_in[2];
    const float* rdt = (const float*)d_in[3];
    const float* wxs = (const float*)d_in[4];
    const float* bxs = (const float*)d_in[5];
    const float* wxt = (const float*)d_in[6];
    const float* bxt = (const float*)d_in[7];

    const float *wfs, *bfs, *wft, *bft;
    const float *rws[4], *rbs[4], *rwt[4], *rbt[4];

    if (in_sizes[8] == PRED * 2 * PRED) {
        wfs = (const float*)d_in[8];  bfs = (const float*)d_in[9];
        wft = (const float*)d_in[10]; bft = (const float*)d_in[11];
        for (int i = 0; i < 4; ++i) {
            rws[i] = (const float*)d_in[12 + 4 * i];
            rbs[i] = (const float*)d_in[13 + 4 * i];
            rwt[i] = (const float*)d_in[14 + 4 * i];
            rbt[i] = (const float*)d_in[15 + 4 * i];
        }
    } else {
        for (int i = 0; i < 4; ++i) {
            rws[i] = (const float*)d_in[8 + i];
            rbs[i] = (const float*)d_in[12 + i];
            rwt[i] = (const float*)d_in[16 + i];
            rbt[i] = (const float*)d_in[20 + i];
        }
        wfs = (const float*)d_in[24]; bfs = (const float*)d_in[25];
        wft = (const float*)d_in[26]; bft = (const float*)d_in[27];
    }

    float* out = (float*)d_out;

    k_prep<<<288, 256>>>(wxs, wxt, wfs, wft,
                         rws[0], rws[1], rws[2], rws[3],
                         rwt[0], rwt[1], rwt[2], rwt[3],
                         bxs, bxt, bfs, bft,
                         rbs[0], rbs[1], rbs[2], rbs[3],
                         rbt[0], rbt[1], rbt[2], rbt[3]);
    k_pgemm<<<76, 128>>>();
    k_main<<<428, 128>>>(x, rds, rdt, idx, out);
}

// round 6
// speedup vs baseline: 3.5055x; 1.4292x over previous
#include <cuda_runtime.h>
#include <cuda_bf16.h>
#include <cstdint>

#define PRED  96
#define SEQ   512
#define NCH   321
#define NB    64
#define KTOT  608
#define NDICT 2000
#define NCOL  20544
#define KC    32
#define NCHUNK 19          // 608 / 32 exact
#define NTILES 161

// ---------------- device scratch ----------------
__device__ float g_bias[PRED];
__device__ float g_B[192 * KTOT];       // [j][col]
__device__ float g_Ax[192 * PRED];      // [j][p]
__device__ float g_Ar[192 * PRED];      // [j][p]
// B in mma-fragment layout: [chunk19][kt2][nt12][lane32][reg2] pairs of bf16
__device__ uint16_t g_Bh[NCHUNK * 3072];
__device__ uint16_t g_Bl[NCHUNK * 3072];

__device__ __forceinline__ void qmap(int q, int &i, int &g, int &dim, int &qq) {
    if (q < 24)      { i = 0; g = 4;  dim = 24; qq = q;      }
    else if (q < 36) { i = 1; g = 8;  dim = 12; qq = q - 24; }
    else if (q < 44) { i = 2; g = 12; dim = 8;  qq = q - 36; }
    else             { i = 3; g = 24; dim = 4;  qq = q - 44; }
}

// ---------------- asm helpers ----------------
__device__ __forceinline__ uint32_t pack_bf16x2(float lo, float hi) {
    uint32_t r;
    asm("cvt.rn.bf16x2.f32 %0, %1, %2;" : "=r"(r) : "f"(hi), "f"(lo));
    return r;
}
__device__ __forceinline__ void sts128(uint32_t a, uint32_t v0, uint32_t v1,
                                       uint32_t v2, uint32_t v3) {
    asm volatile("st.shared.v4.b32 [%0], {%1,%2,%3,%4};"
                 :: "r"(a), "r"(v0), "r"(v1), "r"(v2), "r"(v3));
}
__device__ __forceinline__ void cpa16(uint32_t d, const void* s) {
    asm volatile("cp.async.cg.shared.global [%0], [%1], 16;" :: "r"(d), "l"(s));
}
__device__ __forceinline__ void cp_commit() { asm volatile("cp.async.commit_group;"); }
__device__ __forceinline__ void cp_wait1()  { asm volatile("cp.async.wait_group 1;" ::: "memory"); }
__device__ __forceinline__ void cp_wait0()  { asm volatile("cp.async.wait_group 0;" ::: "memory"); }

__device__ __forceinline__ void ldmat4(uint32_t &a0, uint32_t &a1, uint32_t &a2,
                                       uint32_t &a3, uint32_t addr) {
    asm volatile("ldmatrix.sync.aligned.m8n8.x4.shared.b16 {%0,%1,%2,%3}, [%4];"
                 : "=r"(a0), "=r"(a1), "=r"(a2), "=r"(a3) : "r"(addr));
}
__device__ __forceinline__ void lds64(uint32_t &b0, uint32_t &b1, uint32_t addr) {
    asm volatile("ld.shared.v2.b32 {%0,%1}, [%2];" : "=r"(b0), "=r"(b1) : "r"(addr));
}
__device__ __forceinline__ void mma16816(float* d, uint32_t a0, uint32_t a1,
                                         uint32_t a2, uint32_t a3,
                                         uint32_t b0, uint32_t b1) {
    asm volatile(
        "mma.sync.aligned.m16n8k16.row.col.f32.bf16.bf16.f32 "
        "{%0,%1,%2,%3}, {%4,%5,%6,%7}, {%8,%9}, {%0,%1,%2,%3};"
        : "+f"(d[0]), "+f"(d[1]), "+f"(d[2]), "+f"(d[3])
        : "r"(a0), "r"(a1), "r"(a2), "r"(a3), "r"(b0), "r"(b1));
}

// ================= k_prep (unchanged — validated 6.4us) =================
__global__ void k_prep(const float* __restrict__ wxs, const float* __restrict__ wxt,
    const float* __restrict__ wfs, const float* __restrict__ wft,
    const float* __restrict__ rws0, const float* __restrict__ rws1,
    const float* __restrict__ rws2, const float* __restrict__ rws3,
    const float* __restrict__ rwt0, const float* __restrict__ rwt1,
    const float* __restrict__ rwt2, const float* __restrict__ rwt3,
    const float* __restrict__ bxs,  const float* __restrict__ bxt,
    const float* __restrict__ bfs,  const float* __restrict__ bft,
    const float* __restrict__ rbs0, const float* __restrict__ rbs1,
    const float* __restrict__ rbs2, const float* __restrict__ rbs3,
    const float* __restrict__ rbt0, const float* __restrict__ rbt1,
    const float* __restrict__ rbt2, const float* __restrict__ rbt3) {
    int tid = threadIdx.x;
    if (blockIdx.x >= 192) {
        __shared__ float red[8];
        int p = blockIdx.x - 192;
        float c = 0.f;
        if (tid < 96) {
            int j = tid;
            c = wfs[p * 192 + j] * bxs[j] + wft[p * 192 + j] * bxt[j]
              + wfs[p * 192 + 96 + j] * (rbs0[j] + rbs1[j] + rbs2[j] + rbs3[j])
              + wft[p * 192 + 96 + j] * (rbt0[j] + rbt1[j] + rbt2[j] + rbt3[j]);
        }
        for (int o = 16; o; o >>= 1) c += __shfl_down_sync(0xffffffffu, c, o);
        if ((tid & 31) == 0) red[tid >> 5] = c;
        __syncthreads();
        if (tid == 0) {
            float s = bfs[p] + bft[p];
            #pragma unroll
            for (int i = 0; i < 4; ++i) s += red[i];
            g_bias[p] = s;
        }
        return;
    }
    __shared__ float r[512];
    __shared__ float red[8];
    __shared__ float s_su;
    int j = blockIdx.x;
    int side = j / 96, row = j % 96;
    const float* wx = side ? wxt : wxs;
    r[tid]       = wx[row * SEQ + tid];
    r[tid + 256] = wx[row * SEQ + tid + 256];
    __syncthreads();
    {
        float a = r[tid] + r[tid + 256];
        for (int o = 16; o; o >>= 1) a += __shfl_down_sync(0xffffffffu, a, o);
        if ((tid & 31) == 0) red[tid >> 5] = a;
        __syncthreads();
        if (tid == 0) {
            float s = 0.f;
            #pragma unroll
            for (int i = 0; i < 8; ++i) s += red[i];
            s_su = s;
        }
        __syncthreads();
    }
    float su = s_su;
    #pragma unroll
    for (int t = 0; t < 2; ++t) {
        int l = tid + t * 256;
        int lo = (l - 12 < 0) ? 0 : l - 12;
        int hi = (l + 12 > 511) ? 511 : l + 12;
        float band = 0.f;
        for (int m = lo; m <= hi; ++m) {
            float cnt = 1.f;
            if (l == 0)   cnt = (float)(13 - m);
            if (l == 511) cnt = (float)(m - 498);
            band += cnt * r[m];
        }
        band *= 0.04f;
        float v = side ? band : (r[l] - band);
        float ml = 0.f;
        if (l >= 499 && l <= 510) ml = 0.04f;
        if (l == 511)             ml = 0.52f;
        float coef = side ? (-ml) : (ml - (l == 511 ? 1.f : 0.f));
        v += su * coef;
        g_B[j * KTOT + l] = v;
    }
    if (tid < 96) {
        int q = tid;
        int i, g, dim, qq; qmap(q % 48, i, g, dim, qq);
        float rv = 0.f;
        if ((q / 48) == side) {
            const float* rw;
            if (!side) rw = (i == 0) ? rws0 : (i == 1) ? rws1 : (i == 2) ? rws2 : rws3;
            else       rw = (i == 0) ? rwt0 : (i == 1) ? rwt1 : (i == 2) ? rwt2 : rwt3;
            rv = rw[row * dim + qq];
        }
        g_B[j * KTOT + 512 + q] = rv;
    }
    if (tid < 96) {
        const float* wf = side ? wft : wfs;
        g_Ax[j * 96 + tid] = wf[tid * 192 + row];
        g_Ar[j * 96 + tid] = wf[tid * 192 + 96 + row];
    }
}

// ================= k_pgemm =================
// W[p][col] = sum_j A[j][p]*g_B[j][col] (+1 at col 511); split bf16 hi/lo and
// scatter into mma B-fragment layout (lane = (p%8)*4 + (col%8)/2, reg = (col%16)/8).
__global__ __launch_bounds__(128) void k_pgemm() {
    __shared__ float sA[32 * 96];
    __shared__ float sB[32][8];
    int tid = threadIdx.x;
    int tp = tid >> 2;
    int tc = tid & 3;
    int col0 = blockIdx.x * 8;
    const float* A = (col0 >= 512) ? g_Ar : g_Ax;
    float acc[3][2] = {};
    for (int jc = 0; jc < 6; ++jc) {
        __syncthreads();
        const float4* srcA = reinterpret_cast<const float4*>(A + jc * 32 * 96);
        #pragma unroll
        for (int i = 0; i < 6; ++i)
            reinterpret_cast<float4*>(sA)[tid + i * 128] = srcA[tid + i * 128];
        #pragma unroll
        for (int i = 0; i < 2; ++i) {
            int idx = tid + i * 128;
            int jj = idx >> 3, cc = idx & 7;
            sB[jj][cc] = g_B[(jc * 32 + jj) * KTOT + col0 + cc];
        }
        __syncthreads();
        #pragma unroll 8
        for (int jj = 0; jj < 32; ++jj) {
            float b0 = sB[jj][tc * 2], b1 = sB[jj][tc * 2 + 1];
            #pragma unroll
            for (int u = 0; u < 3; ++u) {
                float a = sA[jj * 96 + tp * 3 + u];
                acc[u][0] += a * b0;
                acc[u][1] += a * b1;
            }
        }
    }
    #pragma unroll
    for (int v = 0; v < 2; ++v) {
        int col = col0 + tc * 2 + v;
        float add = (col == 511) ? 1.f : 0.f;
        #pragma unroll
        for (int u = 0; u < 3; ++u) {
            float val = acc[u][v] + add;
            int p = tp * 3 + u;
            __nv_bfloat16 hb = __float2bfloat16(val);
            float hf = __bfloat162float(hb);
            __nv_bfloat16 lb = __float2bfloat16(val - hf);
            int lane = (p & 7) * 4 + ((col & 7) >> 1);
            int reg  = (col >> 3) & 1;
            long off = ((((long)(col >> 5) * 2 + ((col >> 4) & 1)) * 12 + (p >> 3)) * 32
                        + lane) * 8 + reg * 4 + (col & 1) * 2;
            *(uint16_t*)((char*)g_Bh + off) = __bfloat16_as_ushort(hb);
            *(uint16_t*)((char*)g_Bl + off) = __bfloat16_as_ushort(lb);
        }
    }
}

// ================= k_main: HMMA split-bf16 GEMM =================
// D[128 j, 96 p] per CTA; 8 warps, warp wid owns mtile 16 rows; K=608 in 19x32.
__global__ __launch_bounds__(256, 2) void k_main(
    const float* __restrict__ x, const float* __restrict__ rds,
    const float* __restrict__ rdt, const int* __restrict__ index,
    float* __restrict__ out) {
    __shared__ int sxb[128], sdb[128], sob[128];
    __shared__ const float* qptr[96];
    __shared__ float sbias[96];
    extern __shared__ char dsm_raw[];

    int tid = threadIdx.x;
    int wid = tid >> 5, lane = tid & 31;
    int j0 = blockIdx.x * 128;

    if (tid < 128) {
        int jj = j0 + tid; if (jj > NCOL - 1) jj = NCOL - 1;
        int b = jj / NCH, c = jj - b * NCH;
        sxb[tid] = b * SEQ * NCH + c;
        sob[tid] = b * PRED * NCH + c;
        sdb[tid] = index[b] * PRED * NCH + c;
    }
    if (tid < 96) {
        int q = tid;
        int i, g, dim, qq; qmap(q % 48, i, g, dim, qq);
        const float* base = (q < 48) ? rds : rdt;
        qptr[q] = base + (size_t)i * (NDICT * PRED * NCH) + (size_t)qq * g * NCH;
        sbias[tid] = g_bias[tid];
    }
    __syncthreads();

    // dynamic smem layout (1KB aligned): A rows 80B stride (conflict-free)
    uint32_t db = (uint32_t)__cvta_generic_to_shared(dsm_raw);
    uint32_t ab = (db + 1023u) & ~1023u;
    uint32_t AH[2] = { ab,          ab + 10240 };
    uint32_t AL[2] = { ab + 20480,  ab + 30720 };
    uint32_t BH[2] = { ab + 40960,  ab + 47104 };
    uint32_t BL[2] = { ab + 53248,  ab + 59392 };

    int m  = tid & 127;          // producer column
    int kh = tid >> 7;           // 0/1: k-half of chunk
    const float* xcol = x + sxb[m];
    int dcol = sdb[m];
    uint32_t arow_off = (uint32_t)(m * 80 + kh * 32);

    // ldmatrix lane address precompute
    uint32_t aoff = (uint32_t)((wid * 16 + (lane & 7) + ((lane >> 3) & 1) * 8) * 80
                               + ((lane >> 4) & 1) * 16);
    uint32_t boff = (uint32_t)(lane * 8);

    float acc[12][4];
    #pragma unroll
    for (int nt = 0; nt < 12; ++nt)
        #pragma unroll
        for (int v = 0; v < 4; ++v) acc[nt][v] = 0.f;

    float v[16];

    #define LDGA(cc) do {                                                    \
        int _k0 = (cc) * KC + kh * 16;                                       \
        if (_k0 < 512) {                                                     \
            const float* _s = xcol + (size_t)_k0 * NCH;                      \
            _Pragma("unroll")                                                \
            for (int i_ = 0; i_ < 16; ++i_) v[i_] = _s[i_ * NCH];            \
        } else {                                                             \
            int _q0 = _k0 - 512;                                             \
            _Pragma("unroll")                                                \
            for (int i_ = 0; i_ < 16; ++i_) v[i_] = qptr[_q0 + i_][dcol];    \
        }                                                                    \
    } while (0)

    #define STSA(buf) do {                                                   \
        uint32_t h_[8], l_[8];                                               \
        _Pragma("unroll")                                                    \
        for (int t_ = 0; t_ < 8; ++t_) {                                     \
            uint32_t hp = pack_bf16x2(v[2 * t_], v[2 * t_ + 1]);             \
            float h0 = __uint_as_float(hp << 16);                            \
            float h1 = __uint_as_float(hp & 0xffff0000u);                    \
            uint32_t lp = pack_bf16x2(v[2 * t_] - h0, v[2 * t_ + 1] - h1);   \
            h_[t_] = hp; l_[t_] = lp;                                        \
        }                                                                    \
        sts128(AH[buf] + arow_off,      h_[0], h_[1], h_[2], h_[3]);         \
        sts128(AH[buf] + arow_off + 16, h_[4], h_[5], h_[6], h_[7]);         \
        sts128(AL[buf] + arow_off,      l_[0], l_[1], l_[2], l_[3]);         \
        sts128(AL[buf] + arow_off + 16, l_[4], l_[5], l_[6], l_[7]);         \
    } while (0)

    #define FILLB(buf, cc) do {                                              \
        const char* _sh = (const char*)g_Bh + (size_t)(cc) * 6144;           \
        const char* _sl = (const char*)g_Bl + (size_t)(cc) * 6144;           \
        if (tid < 192) {                                                     \
            uint32_t off = (uint32_t)tid * 16u;                              \
            cpa16(BH[buf] + off, _sh + off);                                 \
            cpa16(BH[buf] + off + 3072, _sh + off + 3072);                   \
            cpa16(BL[buf] + off, _sl + off);                                 \
            cpa16(BL[buf] + off + 3072, _sl + off + 3072);                   \
        }                                                                    \
    } while (0)

    // prologue: fill chunks 0 and 1
    LDGA(0); STSA(0); FILLB(0, 0); cp_commit();
    LDGA(1); STSA(1); FILLB(1, 1); cp_commit();
    cp_wait1();
    __syncthreads();

    #pragma unroll 1
    for (int c = 0; c < NCHUNK; ++c) {
        int cur = c & 1;
        bool pre = (c + 2 < NCHUNK);
        if (pre) LDGA(c + 2);                      // hide DRAM latency under mma

        // ---- compute chunk c ----
        #pragma unroll
        for (int kt = 0; kt < 2; ++kt) {
            uint32_t ah0, ah1, ah2, ah3, al0, al1, al2, al3;
            ldmat4(ah0, ah1, ah2, ah3, AH[cur] + aoff + kt * 32);
            ldmat4(al0, al1, al2, al3, AL[cur] + aoff + kt * 32);
            uint32_t bbh = BH[cur] + (uint32_t)(kt * 3072) + boff;
            uint32_t bbl = BL[cur] + (uint32_t)(kt * 3072) + boff;
            #pragma unroll
            for (int nt = 0; nt < 12; ++nt) {
                uint32_t bh0, bh1, bl0, bl1;
                lds64(bh0, bh1, bbh + nt * 256);
                lds64(bl0, bl1, bbl + nt * 256);
                mma16816(acc[nt], ah0, ah1, ah2, ah3, bh0, bh1);
                mma16816(acc[nt], ah0, ah1, ah2, ah3, bl0, bl1);
                mma16816(acc[nt], al0, al1, al2, al3, bh0, bh1);
            }
        }
        __syncthreads();
        if (pre) {
            STSA(cur); FILLB(cur, c + 2); cp_commit(); cp_wait1();
        } else {
            cp_wait0();
        }
        __syncthreads();
    }
    #undef LDGA
    #undef STSA
    #undef FILLB

    // ---- epilogue ----
    int g = lane >> 2, tg = lane & 3;
    int r0 = wid * 16 + g, r1 = r0 + 8;
    bool v0 = (j0 + r0) < NCOL, v1 = (j0 + r1) < NCOL;
    int ob0 = sob[r0], ob1 = sob[r1];
    #pragma unroll
    for (int nt = 0; nt < 12; ++nt) {
        int p0 = nt * 8 + tg * 2;
        float sb0 = sbias[p0], sb1 = sbias[p0 + 1];
        if (v0) {
            out[ob0 + p0 * NCH]       = acc[nt][0] + sb0;
            out[ob0 + (p0 + 1) * NCH] = acc[nt][1] + sb1;
        }
        if (v1) {
            out[ob1 + p0 * NCH]       = acc[nt][2] + sb0;
            out[ob1 + (p0 + 1) * NCH] = acc[nt][3] + sb1;
        }
    }
}

// ---------------- launch ----------------
#define DSM_BYTES (65536 + 1024)

extern "C" void kernel_launch(void* const* d_in, const int* in_sizes, int n_in,
                              void* d_out, int out_size) {
    const float* x   = (const float*)d_in[0];
    const int*   idx = (const int*)d_in[1];
    const float* rds = (const float*)d_in[2];
    const float* rdt = (const float*)d_in[3];
    const float* wxs = (const float*)d_in[4];
    const float* bxs = (const float*)d_in[5];
    const float* wxt = (const float*)d_in[6];
    const float* bxt = (const float*)d_in[7];

    const float *wfs, *bfs, *wft, *bft;
    const float *rws[4], *rbs[4], *rwt[4], *rbt[4];

    if (in_sizes[8] == PRED * 2 * PRED) {
        wfs = (const float*)d_in[8];  bfs = (const float*)d_in[9];
        wft = (const float*)d_in[10]; bft = (const float*)d_in[11];
        for (int i = 0; i < 4; ++i) {
            rws[i] = (const float*)d_in[12 + 4 * i];
            rbs[i] = (const float*)d_in[13 + 4 * i];
            rwt[i] = (const float*)d_in[14 + 4 * i];
            rbt[i] = (const float*)d_in[15 + 4 * i];
        }
    } else {
        for (int i = 0; i < 4; ++i) {
            rws[i] = (const float*)d_in[8 + i];
            rbs[i] = (const float*)d_in[12 + i];
            rwt[i] = (const float*)d_in[16 + i];
            rbt[i] = (const float*)d_in[20 + i];
        }
        wfs = (const float*)d_in[24]; bfs = (const float*)d_in[25];
        wft = (const float*)d_in[26]; bft = (const float*)d_in[27];
    }

    float* out = (float*)d_out;

    cudaFuncSetAttribute(k_main, cudaFuncAttributeMaxDynamicSharedMemorySize,
                         DSM_BYTES);

    k_prep<<<288, 256>>>(wxs, wxt, wfs, wft,
                         rws[0], rws[1], rws[2], rws[3],
                         rwt[0], rwt[1], rwt[2], rwt[3],
                         bxs, bxt, bfs, bft,
                         rbs[0], rbs[1], rbs[2], rbs[3],
                         rbt[0], rbt[1], rbt[2], rbt[3]);
    k_pgemm<<<76, 128>>>();
    k_main<<<NTILES, 256, DSM_BYTES>>>(x, rds, rdt, idx, out);
}

// round 7
// speedup vs baseline: 5.1487x; 1.4687x over previous
#include <cuda_runtime.h>
#include <cuda_bf16.h>
#include <cuda_fp16.h>
#include <cstdint>

#define PRED  96
#define SEQ   512
#define NCH   321
#define NB    64
#define KTOT  608
#define NDICT 2000
#define NCOL  20544
#define KC    32
#define NCHUNK 19          // 608 / 32 exact
#define NTILES 321         // 20544 / 64 exact

// ---------------- device scratch ----------------
__device__ float g_bias[PRED];
__device__ float g_B[192 * KTOT];       // [j][col]
__device__ float g_Ax[192 * PRED];      // [j][p]
__device__ float g_Ar[192 * PRED];      // [j][p]
// W in mma-fragment layout, fp16: [chunk19][kt2][nt12][lane32][reg2] pairs
__device__ uint16_t g_Bf[NCHUNK * 3072];

__device__ __forceinline__ void qmap(int q, int &i, int &g, int &dim, int &qq) {
    if (q < 24)      { i = 0; g = 4;  dim = 24; qq = q;      }
    else if (q < 36) { i = 1; g = 8;  dim = 12; qq = q - 24; }
    else if (q < 44) { i = 2; g = 12; dim = 8;  qq = q - 36; }
    else             { i = 3; g = 24; dim = 4;  qq = q - 44; }
}

// ---------------- asm helpers ----------------
__device__ __forceinline__ uint32_t pack_f16x2(float lo, float hi) {
    uint32_t r;
    asm("cvt.rn.f16x2.f32 %0, %1, %2;" : "=r"(r) : "f"(hi), "f"(lo));
    return r;
}
__device__ __forceinline__ void sts128(uint32_t a, uint32_t v0, uint32_t v1,
                                       uint32_t v2, uint32_t v3) {
    asm volatile("st.shared.v4.b32 [%0], {%1,%2,%3,%4};"
                 :: "r"(a), "r"(v0), "r"(v1), "r"(v2), "r"(v3));
}
__device__ __forceinline__ void cpa16(uint32_t d, const void* s) {
    asm volatile("cp.async.cg.shared.global [%0], [%1], 16;" :: "r"(d), "l"(s));
}
__device__ __forceinline__ void cp_commit() { asm volatile("cp.async.commit_group;"); }
__device__ __forceinline__ void cp_wait1()  { asm volatile("cp.async.wait_group 1;" ::: "memory"); }
__device__ __forceinline__ void cp_wait0()  { asm volatile("cp.async.wait_group 0;" ::: "memory"); }

__device__ __forceinline__ void ldmat4(uint32_t &a0, uint32_t &a1, uint32_t &a2,
                                       uint32_t &a3, uint32_t addr) {
    asm volatile("ldmatrix.sync.aligned.m8n8.x4.shared.b16 {%0,%1,%2,%3}, [%4];"
                 : "=r"(a0), "=r"(a1), "=r"(a2), "=r"(a3) : "r"(addr));
}
__device__ __forceinline__ void lds64(uint32_t &b0, uint32_t &b1, uint32_t addr) {
    asm volatile("ld.shared.v2.b32 {%0,%1}, [%2];" : "=r"(b0), "=r"(b1) : "r"(addr));
}
__device__ __forceinline__ void mma16816(float* d, uint32_t a0, uint32_t a1,
                                         uint32_t a2, uint32_t a3,
                                         uint32_t b0, uint32_t b1) {
    asm volatile(
        "mma.sync.aligned.m16n8k16.row.col.f32.f16.f16.f32 "
        "{%0,%1,%2,%3}, {%4,%5,%6,%7}, {%8,%9}, {%0,%1,%2,%3};"
        : "+f"(d[0]), "+f"(d[1]), "+f"(d[2]), "+f"(d[3])
        : "r"(a0), "r"(a1), "r"(a2), "r"(a3), "r"(b0), "r"(b1));
}

// ================= k_prep (validated — 6.2us) =================
__global__ void k_prep(const float* __restrict__ wxs, const float* __restrict__ wxt,
    const float* __restrict__ wfs, const float* __restrict__ wft,
    const float* __restrict__ rws0, const float* __restrict__ rws1,
    const float* __restrict__ rws2, const float* __restrict__ rws3,
    const float* __restrict__ rwt0, const float* __restrict__ rwt1,
    const float* __restrict__ rwt2, const float* __restrict__ rwt3,
    const float* __restrict__ bxs,  const float* __restrict__ bxt,
    const float* __restrict__ bfs,  const float* __restrict__ bft,
    const float* __restrict__ rbs0, const float* __restrict__ rbs1,
    const float* __restrict__ rbs2, const float* __restrict__ rbs3,
    const float* __restrict__ rbt0, const float* __restrict__ rbt1,
    const float* __restrict__ rbt2, const float* __restrict__ rbt3) {
    int tid = threadIdx.x;
    if (blockIdx.x >= 192) {
        __shared__ float red[8];
        int p = blockIdx.x - 192;
        float c = 0.f;
        if (tid < 96) {
            int j = tid;
            c = wfs[p * 192 + j] * bxs[j] + wft[p * 192 + j] * bxt[j]
              + wfs[p * 192 + 96 + j] * (rbs0[j] + rbs1[j] + rbs2[j] + rbs3[j])
              + wft[p * 192 + 96 + j] * (rbt0[j] + rbt1[j] + rbt2[j] + rbt3[j]);
        }
        for (int o = 16; o; o >>= 1) c += __shfl_down_sync(0xffffffffu, c, o);
        if ((tid & 31) == 0) red[tid >> 5] = c;
        __syncthreads();
        if (tid == 0) {
            float s = bfs[p] + bft[p];
            #pragma unroll
            for (int i = 0; i < 4; ++i) s += red[i];
            g_bias[p] = s;
        }
        return;
    }
    __shared__ float r[512];
    __shared__ float red[8];
    __shared__ float s_su;
    int j = blockIdx.x;
    int side = j / 96, row = j % 96;
    const float* wx = side ? wxt : wxs;
    r[tid]       = wx[row * SEQ + tid];
    r[tid + 256] = wx[row * SEQ + tid + 256];
    __syncthreads();
    {
        float a = r[tid] + r[tid + 256];
        for (int o = 16; o; o >>= 1) a += __shfl_down_sync(0xffffffffu, a, o);
        if ((tid & 31) == 0) red[tid >> 5] = a;
        __syncthreads();
        if (tid == 0) {
            float s = 0.f;
            #pragma unroll
            for (int i = 0; i < 8; ++i) s += red[i];
            s_su = s;
        }
        __syncthreads();
    }
    float su = s_su;
    #pragma unroll
    for (int t = 0; t < 2; ++t) {
        int l = tid + t * 256;
        int lo = (l - 12 < 0) ? 0 : l - 12;
        int hi = (l + 12 > 511) ? 511 : l + 12;
        float band = 0.f;
        for (int m = lo; m <= hi; ++m) {
            float cnt = 1.f;
            if (l == 0)   cnt = (float)(13 - m);
            if (l == 511) cnt = (float)(m - 498);
            band += cnt * r[m];
        }
        band *= 0.04f;
        float v = side ? band : (r[l] - band);
        float ml = 0.f;
        if (l >= 499 && l <= 510) ml = 0.04f;
        if (l == 511)             ml = 0.52f;
        float coef = side ? (-ml) : (ml - (l == 511 ? 1.f : 0.f));
        v += su * coef;
        g_B[j * KTOT + l] = v;
    }
    if (tid < 96) {
        int q = tid;
        int i, g, dim, qq; qmap(q % 48, i, g, dim, qq);
        float rv = 0.f;
        if ((q / 48) == side) {
            const float* rw;
            if (!side) rw = (i == 0) ? rws0 : (i == 1) ? rws1 : (i == 2) ? rws2 : rws3;
            else       rw = (i == 0) ? rwt0 : (i == 1) ? rwt1 : (i == 2) ? rwt2 : rwt3;
            rv = rw[row * dim + qq];
        }
        g_B[j * KTOT + 512 + q] = rv;
    }
    if (tid < 96) {
        const float* wf = side ? wft : wfs;
        g_Ax[j * 96 + tid] = wf[tid * 192 + row];
        g_Ar[j * 96 + tid] = wf[tid * 192 + 96 + row];
    }
}

// ================= k_pgemm =================
// W[p][col] = sum_j A[j][p]*g_B[j][col] (+1 at col 511); round to fp16 and
// scatter into mma B-fragment layout (validated in R6).
__global__ __launch_bounds__(128) void k_pgemm() {
    __shared__ float sA[32 * 96];
    __shared__ float sB[32][8];
    int tid = threadIdx.x;
    int tp = tid >> 2;
    int tc = tid & 3;
    int col0 = blockIdx.x * 8;
    const float* A = (col0 >= 512) ? g_Ar : g_Ax;
    float acc[3][2] = {};
    for (int jc = 0; jc < 6; ++jc) {
        __syncthreads();
        const float4* srcA = reinterpret_cast<const float4*>(A + jc * 32 * 96);
        #pragma unroll
        for (int i = 0; i < 6; ++i)
            reinterpret_cast<float4*>(sA)[tid + i * 128] = srcA[tid + i * 128];
        #pragma unroll
        for (int i = 0; i < 2; ++i) {
            int idx = tid + i * 128;
            int jj = idx >> 3, cc = idx & 7;
            sB[jj][cc] = g_B[(jc * 32 + jj) * KTOT + col0 + cc];
        }
        __syncthreads();
        #pragma unroll 8
        for (int jj = 0; jj < 32; ++jj) {
            float b0 = sB[jj][tc * 2], b1 = sB[jj][tc * 2 + 1];
            #pragma unroll
            for (int u = 0; u < 3; ++u) {
                float a = sA[jj * 96 + tp * 3 + u];
                acc[u][0] += a * b0;
                acc[u][1] += a * b1;
            }
        }
    }
    #pragma unroll
    for (int v = 0; v < 2; ++v) {
        int col = col0 + tc * 2 + v;
        float add = (col == 511) ? 1.f : 0.f;
        #pragma unroll
        for (int u = 0; u < 3; ++u) {
            float val = acc[u][v] + add;
            int p = tp * 3 + u;
            __half hv = __float2half(val);
            int lane = (p & 7) * 4 + ((col & 7) >> 1);
            int reg  = (col >> 3) & 1;
            long off = ((((long)(col >> 5) * 2 + ((col >> 4) & 1)) * 12 + (p >> 3)) * 32
                        + lane) * 8 + reg * 4 + (col & 1) * 2;
            *(uint16_t*)((char*)g_Bf + off) = __half_as_ushort(hv);
        }
    }
}

// ================= k_main: single-fp16 HMMA GEMM =================
// D[64 j, 96 p] per CTA; grid 321 (exact); 8 warps = 4 m-tiles x 2 n-groups.
__global__ __launch_bounds__(256, 3) void k_main(
    const float* __restrict__ x, const float* __restrict__ rds,
    const float* __restrict__ rdt, const int* __restrict__ index,
    float* __restrict__ out) {
    __shared__ int sxb[64], sdb[64], sob[64];
    __shared__ const float* qptr[96];
    __shared__ float sbias[96];
    extern __shared__ char dsm_raw[];

    int tid = threadIdx.x;
    int wid = tid >> 5, lane = tid & 31;
    int j0 = blockIdx.x * 64;

    if (tid < 64) {
        int jj = j0 + tid;
        int b = jj / NCH, c = jj - b * NCH;
        sxb[tid] = b * SEQ * NCH + c;
        sob[tid] = b * PRED * NCH + c;
        sdb[tid] = index[b] * PRED * NCH + c;
    }
    if (tid < 96) {
        int q = tid;
        int i, g, dim, qq; qmap(q % 48, i, g, dim, qq);
        const float* base = (q < 48) ? rds : rdt;
        qptr[q] = base + (size_t)i * (NDICT * PRED * NCH) + (size_t)qq * g * NCH;
        sbias[tid] = g_bias[tid];
    }
    __syncthreads();

    uint32_t db = (uint32_t)__cvta_generic_to_shared(dsm_raw);
    uint32_t ab = (db + 1023u) & ~1023u;
    uint32_t AF[2] = { ab,          ab + 5120 };    // 64 rows x 80B
    uint32_t BF[2] = { ab + 10240,  ab + 16384 };   // 6144B each

    int m  = tid & 63;           // producer column
    int kh = tid >> 6;           // 0..3: k-octet of chunk
    const float* xcol = x + sxb[m];
    int dcol = sdb[m];
    uint32_t arow_off = (uint32_t)(m * 80 + kh * 16);

    int mw = wid & 3;            // m-tile (16 rows)
    int ng = wid >> 2;           // n-group: nt 6*ng .. 6*ng+5
    uint32_t aoff = (uint32_t)((mw * 16 + (lane & 7) + ((lane >> 3) & 1) * 8) * 80
                               + ((lane >> 4) & 1) * 16);
    uint32_t boff = (uint32_t)(ng * 6 * 256 + lane * 8);

    float acc[6][4];
    #pragma unroll
    for (int nt = 0; nt < 6; ++nt)
        #pragma unroll
        for (int v = 0; v < 4; ++v) acc[nt][v] = 0.f;

    float v[8];

    #define LDGA(cc) do {                                                    \
        int _k0 = (cc) * KC + kh * 8;                                        \
        if (_k0 < 512) {                                                     \
            const float* _s = xcol + (size_t)_k0 * NCH;                      \
            _Pragma("unroll")                                                \
            for (int i_ = 0; i_ < 8; ++i_) v[i_] = _s[i_ * NCH];             \
        } else {                                                             \
            int _q0 = _k0 - 512;                                             \
            _Pragma("unroll")                                                \
            for (int i_ = 0; i_ < 8; ++i_) v[i_] = qptr[_q0 + i_][dcol];     \
        }                                                                    \
    } while (0)

    #define STSA(buf) do {                                                   \
        uint32_t h_[4];                                                      \
        _Pragma("unroll")                                                    \
        for (int t_ = 0; t_ < 4; ++t_)                                       \
            h_[t_] = pack_f16x2(v[2 * t_], v[2 * t_ + 1]);                   \
        sts128(AF[buf] + arow_off, h_[0], h_[1], h_[2], h_[3]);              \
    } while (0)

    #define FILLB(buf, cc) do {                                              \
        const char* _sf = (const char*)g_Bf + (size_t)(cc) * 6144;           \
        if (tid < 192) {                                                     \
            uint32_t off = (uint32_t)tid * 16u;                              \
            cpa16(BF[buf] + off, _sf + off);                                 \
            cpa16(BF[buf] + off + 3072, _sf + off + 3072);                   \
        }                                                                    \
    } while (0)

    LDGA(0); STSA(0); FILLB(0, 0); cp_commit();
    LDGA(1); STSA(1); FILLB(1, 1); cp_commit();
    cp_wait1();
    __syncthreads();

    #pragma unroll 1
    for (int c = 0; c < NCHUNK; ++c) {
        int cur = c & 1;
        bool pre = (c + 2 < NCHUNK);
        if (pre) LDGA(c + 2);                      // hide DRAM latency under mma

        #pragma unroll
        for (int kt = 0; kt < 2; ++kt) {
            uint32_t a0, a1, a2, a3;
            ldmat4(a0, a1, a2, a3, AF[cur] + aoff + kt * 32);
            uint32_t bb = BF[cur] + (uint32_t)(kt * 3072) + boff;
            #pragma unroll
            for (int nt = 0; nt < 6; ++nt) {
                uint32_t b0, b1;
                lds64(b0, b1, bb + nt * 256);
                mma16816(acc[nt], a0, a1, a2, a3, b0, b1);
            }
        }
        __syncthreads();
        if (pre) {
            STSA(cur); FILLB(cur, c + 2); cp_commit(); cp_wait1();
        } else {
            cp_wait0();
        }
        __syncthreads();
    }
    #undef LDGA
    #undef STSA
    #undef FILLB

    // ---- epilogue ----
    int g = lane >> 2, tg = lane & 3;
    int r0 = mw * 16 + g, r1 = r0 + 8;
    int ob0 = sob[r0], ob1 = sob[r1];
    #pragma unroll
    for (int nt = 0; nt < 6; ++nt) {
        int p0 = (ng * 6 + nt) * 8 + tg * 2;
        float sb0 = sbias[p0], sb1 = sbias[p0 + 1];
        out[ob0 + p0 * NCH]       = acc[nt][0] + sb0;
        out[ob0 + (p0 + 1) * NCH] = acc[nt][1] + sb1;
        out[ob1 + p0 * NCH]       = acc[nt][2] + sb0;
        out[ob1 + (p0 + 1) * NCH] = acc[nt][3] + sb1;
    }
}

// ---------------- launch ----------------
#define DSM_BYTES (22528 + 1024)

extern "C" void kernel_launch(void* const* d_in, const int* in_sizes, int n_in,
                              void* d_out, int out_size) {
    const float* x   = (const float*)d_in[0];
    const int*   idx = (const int*)d_in[1];
    const float* rds = (const float*)d_in[2];
    const float* rdt = (const float*)d_in[3];
    const float* wxs = (const float*)d_in[4];
    const float* bxs = (const float*)d_in[5];
    const float* wxt = (const float*)d_in[6];
    const float* bxt = (const float*)d_in[7];

    const float *wfs, *bfs, *wft, *bft;
    const float *rws[4], *rbs[4], *rwt[4], *rbt[4];

    if (in_sizes[8] == PRED * 2 * PRED) {
        wfs = (const float*)d_in[8];  bfs = (const float*)d_in[9];
        wft = (const float*)d_in[10]; bft = (const float*)d_in[11];
        for (int i = 0; i < 4; ++i) {
            rws[i] = (const float*)d_in[12 + 4 * i];
            rbs[i] = (const float*)d_in[13 + 4 * i];
            rwt[i] = (const float*)d_in[14 + 4 * i];
            rbt[i] = (const float*)d_in[15 + 4 * i];
        }
    } else {
        for (int i = 0; i < 4; ++i) {
            rws[i] = (const float*)d_in[8 + i];
            rbs[i] = (const float*)d_in[12 + i];
            rwt[i] = (const float*)d_in[16 + i];
            rbt[i] = (const float*)d_in[20 + i];
        }
        wfs = (const float*)d_in[24]; bfs = (const float*)d_in[25];
        wft = (const float*)d_in[26]; bft = (const float*)d_in[27];
    }

    float* out = (float*)d_out;

    cudaFuncSetAttribute(k_main, cudaFuncAttributeMaxDynamicSharedMemorySize,
                         DSM_BYTES);

    k_prep<<<288, 256>>>(wxs, wxt, wfs, wft,
                         rws[0], rws[1], rws[2], rws[3],
                         rwt[0], rwt[1], rwt[2], rwt[3],
                         bxs, bxt, bfs, bft,
                         rbs[0], rbs[1], rbs[2], rbs[3],
                         rbt[0], rbt[1], rbt[2], rbt[3]);
    k_pgemm<<<76, 128>>>();
    k_main<<<NTILES, 256, DSM_BYTES>>>(x, rds, rdt, idx, out);
}